// round 9
// baseline (speedup 1.0000x reference)
#include <cuda_runtime.h>
#include <cuda_bf16.h>
#include <cstdint>

// Problem constants
#define B_DIM   2048
#define P_DIM   50
#define K_DIM   28672            // 512*7*8
#define NP      56               // P padded to 56 (7 n8-tiles)
#define KS      28               // K splits (uniform NITER=32, grid 448)
#define KCHUNK  (K_DIM / KS)     // 1024
#define KB      32               // K floats per pipeline stage
#define NITER   (KCHUNK / KB)    // 32
#define MT      128              // M tile
#define MTILES  (B_DIM / MT)     // 16
#define STAGES  3
#define BPITCH  40               // bf16 pitch for B tile (80 B rows, conflict-free)

#define AS_BYTES (MT * KB * 4)               // 16384 (fp32 A, XOR swizzle, 128B rows)
#define BS_BYTES (NP * BPITCH * 2)           // 4480  (bf16 B)
#define STAGE_BYTES (AS_BYTES + BS_BYTES)    // 20864
#define SMEM_BYTES (STAGES * STAGE_BYTES)    // 62592 -> 3 CTAs/SM comfortably

// Static device scratch (allocation-free rule)
__device__ __nv_bfloat16 g_xp[(size_t)KS * MTILES * MT * NP];   // 6.4 MB (bf16)
__device__ float g_x2[(size_t)KS * B_DIM];                       // 229 KB
__device__ float g_p2p[KS][NP];                                  // p2 partials per ks

// ---------------------------------------------------------------------------
__device__ __forceinline__ void cpa16(uint32_t saddr, const void* gaddr) {
    asm volatile("cp.async.cg.shared.global [%0], [%1], 16;\n"
                 :: "r"(saddr), "l"(gaddr));
}
__device__ __forceinline__ void cpa_commit() {
    asm volatile("cp.async.commit_group;\n" ::: "memory");
}
__device__ __forceinline__ void cpa_wait2() {
    asm volatile("cp.async.wait_group 2;\n" ::: "memory");
}
__device__ __forceinline__ uint32_t pack_bf16x2(float2 v) {
    __nv_bfloat162 h = __floats2bfloat162_rn(v.x, v.y);
    return *(uint32_t*)&h;
}

// ---------------------------------------------------------------------------
// Fused GEMM:
//  - A (x) fp32 via cp.async, 3 stages, XOR-swizzled 128B rows (R8-proven)
//  - B (proto) LDG fp32 from L2 -> reg convert -> STS bf16 (BPITCH=40, R2-proven)
//  - x^2 from A fragments; p^2 from producer registers (mt==0 blocks)
// grid (MTILES, KS) = 448 blocks, 256 threads = 8 warps.
// Skeleton: sync -> {stsB, cp.async A, ldg B(it+3)} -> wait2 -> sync -> compute
// ---------------------------------------------------------------------------
__global__ void __launch_bounds__(256, 3) gemm_kernel(
        const float* __restrict__ x, const float* __restrict__ proto) {
    extern __shared__ char smem[];

    const int mt   = blockIdx.x;
    const int ks   = blockIdx.y;
    const int t    = threadIdx.x;
    const int warp = t >> 5;
    const int lane = t & 31;
    const int q    = lane & 3;
    const int rr   = lane >> 2;       // 0..7
    const int b0   = mt * MT;
    const int k0   = ks * KCHUNK;

    // --- A cp.async mapping (unchanged from R8) ---
    const int xrr = t >> 3;           // 0..31
    const int xch = t & 7;            // 16B granule 0..7
    const float* xg0 = x + (size_t)(b0 + xrr) * K_DIM + k0 + xch * 4;
    const uint32_t a_sw = (uint32_t)(xch ^ ((xrr & 3) << 1));
    const uint32_t smem_u = (uint32_t)__cvta_generic_to_shared(smem);

    auto issueA = [&](int stage, int chunk) {
        const uint32_t sb = smem_u + (uint32_t)(stage * STAGE_BYTES);
        const float* xg = xg0 + chunk * KB;
        #pragma unroll
        for (int pass = 0; pass < 4; pass++) {
            cpa16(sb + (uint32_t)((xrr + pass * 32) * 128) + (a_sw << 4),
                  xg + (size_t)(pass * 32) * K_DIM);
        }
    };

    // --- B producer mapping: 448 granules (56 rows x 8), thread t owns
    //     granule t (row rA=t>>3, always < P_DIM) and granule t+256 (row rB=rA+32)
    const int rA = t >> 3;            // 0..31
    const int gA = t & 7;
    const bool hB  = (t < 192);       // second granule exists (rows 32..55)
    const int rB = rA + 32;
    const bool ldB = hB && (rB < P_DIM);
    const float* pgA = proto + (size_t)rA * K_DIM + k0 + gA * 4;
    const float* pgB = proto + (size_t)rB * K_DIM + k0 + gA * 4;
    float p2A = 0.f, p2B = 0.f;

    float4 cA, cB;
    auto ldchunk = [&](int chunk) {
        cA = *(const float4*)(pgA + chunk * KB);
        p2A += cA.x * cA.x + cA.y * cA.y + cA.z * cA.z + cA.w * cA.w;
        cB = make_float4(0.f, 0.f, 0.f, 0.f);
        if (ldB) {
            cB = *(const float4*)(pgB + chunk * KB);
            p2B += cB.x * cB.x + cB.y * cB.y + cB.z * cB.z + cB.w * cB.w;
        }
    };
    auto stsB = [&](int stage) {
        char* sb = smem + stage * STAGE_BYTES + AS_BYTES;
        *(uint2*)(sb + rA * 80 + gA * 8) =
            make_uint2(pack_bf16x2(make_float2(cA.x, cA.y)),
                       pack_bf16x2(make_float2(cA.z, cA.w)));
        if (hB)
            *(uint2*)(sb + rB * 80 + gA * 8) =
                make_uint2(pack_bf16x2(make_float2(cB.x, cB.y)),
                           pack_bf16x2(make_float2(cB.z, cB.w)));
    };

    // prologue: B chunks 0,1 into stages 0,1; hold chunk 2 in regs; A stages 0,1
    ldchunk(0); stsB(0);
    ldchunk(1); stsB(1);
    ldchunk(2);
    issueA(0, 0); cpa_commit();
    issueA(1, 1); cpa_commit();

    // fragment rows
    const int r0 = warp * 16 + rr;
    const int r1 = r0 + 8;
    const uint32_t swf = (uint32_t)((rr & 3) << 1);
    const int qg = q >> 1;
    const int qp = (q & 1) << 3;

    float acc[7][4];
    #pragma unroll
    for (int j = 0; j < 7; j++)
        #pragma unroll
        for (int c = 0; c < 4; c++) acc[j][c] = 0.f;
    float x2a = 0.f, x2b = 0.f;

    int stage = 0;
    for (int it = 0; it < NITER; ++it) {
        __syncthreads();                 // stage (it+2)%3 free to overwrite
        const int nxt = it + 2;
        const int s2 = (stage + 2 >= STAGES) ? stage - 1 : stage + 2;
        if (nxt < NITER) {
            stsB(s2);                    // B chunk it+2 (held in regs) -> smem
            issueA(s2, nxt);
            cpa_commit();
            if (it + 3 < NITER) ldchunk(it + 3);
        } else {
            cpa_commit();                // keep group counting uniform
        }
        cpa_wait2();                     // my A copies for chunk `it` complete
        __syncthreads();                 // ALL threads' copies/STS visible

        const char* sb = smem + stage * STAGE_BYTES;
        const __nv_bfloat16* b_s = (const __nv_bfloat16*)(sb + AS_BYTES);
        if (++stage == STAGES) stage = 0;

        #pragma unroll
        for (int kk = 0; kk < 2; ++kk) {
            const uint32_t g0 = (uint32_t)(kk * 4 + qg);
            const uint32_t o_lo = ((g0 ^ swf) << 4) + qp;
            const uint32_t o_hi = (((g0 + 2) ^ swf) << 4) + qp;
            float2 a00 = *(const float2*)(sb + r0 * 128 + o_lo);
            float2 a01 = *(const float2*)(sb + r0 * 128 + o_hi);
            float2 a10 = *(const float2*)(sb + r1 * 128 + o_lo);
            float2 a11 = *(const float2*)(sb + r1 * 128 + o_hi);
            x2a += a00.x * a00.x + a00.y * a00.y + a01.x * a01.x + a01.y * a01.y;
            x2b += a10.x * a10.x + a10.y * a10.y + a11.x * a11.x + a11.y * a11.y;
            uint32_t A0 = pack_bf16x2(a00);
            uint32_t A1 = pack_bf16x2(a10);
            uint32_t A2 = pack_bf16x2(a01);
            uint32_t A3 = pack_bf16x2(a11);
            const int kb = kk * 16 + q * 2;
            #pragma unroll
            for (int j = 0; j < 7; j++) {
                const int n = j * 8 + rr;
                uint32_t B0 = *(const uint32_t*)&b_s[n * BPITCH + kb];
                uint32_t B1 = *(const uint32_t*)&b_s[n * BPITCH + kb + 8];
                asm volatile(
                    "mma.sync.aligned.m16n8k16.row.col.f32.bf16.bf16.f32 "
                    "{%0,%1,%2,%3}, {%4,%5,%6,%7}, {%8,%9}, {%0,%1,%2,%3};\n"
                    : "+f"(acc[j][0]), "+f"(acc[j][1]), "+f"(acc[j][2]), "+f"(acc[j][3])
                    : "r"(A0), "r"(A1), "r"(A2), "r"(A3), "r"(B0), "r"(B1));
            }
        }
    }

    // xp partials in bf16 (private scratch slice per block — deterministic)
    __nv_bfloat16* outp = g_xp + ((size_t)ks * MTILES + mt) * (MT * NP);
    const int ccol = q * 2;
    #pragma unroll
    for (int j = 0; j < 7; j++) {
        const int n = j * 8 + ccol;
        *(uint32_t*)&outp[(size_t)r0 * NP + n] = pack_bf16x2(make_float2(acc[j][0], acc[j][1]));
        *(uint32_t*)&outp[(size_t)r1 * NP + n] = pack_bf16x2(make_float2(acc[j][2], acc[j][3]));
    }

    // x^2 partials: quad reduce (lanes differ only in k coverage)
    x2a += __shfl_xor_sync(0xffffffffu, x2a, 1);
    x2a += __shfl_xor_sync(0xffffffffu, x2a, 2);
    x2b += __shfl_xor_sync(0xffffffffu, x2b, 1);
    x2b += __shfl_xor_sync(0xffffffffu, x2b, 2);
    if (q == 0) {
        g_x2[(size_t)ks * B_DIM + b0 + r0] = x2a;
        g_x2[(size_t)ks * B_DIM + b0 + r1] = x2b;
    }

    // p^2 partials (producer-side, exact fp32): reduce 8 granule-threads per row
    if (mt == 0) {
        __syncthreads();                       // done with stage smem
        float* f = (float*)smem;               // reuse stage0 region (disjoint from stage1)
        f[t] = p2A;
        if (hB) f[256 + t] = p2B;
        __syncthreads();
        if (t < NP) {
            const int base = (t < 32) ? t * 8 : 256 + (t - 32) * 8;
            float s = 0.f;
            #pragma unroll
            for (int g = 0; g < 8; g++) s += f[base + g];
            g_p2p[ks][t] = s;
        }
    }
}

// ---------------------------------------------------------------------------
// Epilogue: 128 blocks x 256 threads; block = (mt, 16-row group).
// Phase 1: reduce x2 (and p2) into smem. Phase 2: coalesced bf16x2 xp loads.
// ---------------------------------------------------------------------------
__global__ void __launch_bounds__(256) epilogue_kernel(float* __restrict__ out) {
    const int blk = blockIdx.x;        // 0..127
    const int mtb = blk >> 3;          // 0..15
    const int rg  = blk & 7;           // 0..7  (16-row group)
    const int t   = threadIdx.x;
    const int rbase = mtb * 128 + rg * 16;

    __shared__ float xtmp[448];        // [ks 28][row 16]
    __shared__ float x2s[16];
    __shared__ float p2s[NP];

    // phase 1a: load x2 partials (coalesced 64B per ks)
    {
        int ksi = t >> 4, row = t & 15;
        xtmp[t] = g_x2[(size_t)ksi * B_DIM + rbase + row];
        if (t < 192) {
            int i = t + 256;
            ksi = i >> 4; row = i & 15;
            xtmp[i] = g_x2[(size_t)ksi * B_DIM + rbase + row];
        }
    }
    __syncthreads();
    // phase 1b: reduce x2 per row; reduce p2 per p (disjoint thread ranges)
    if (t < 16) {
        float s = 0.f;
        #pragma unroll
        for (int i = 0; i < KS; i++) s += xtmp[i * 16 + t];
        x2s[t] = s;
    } else if (t >= 32 && t < 32 + NP) {
        const int p = t - 32;
        float s = 0.f;
        #pragma unroll
        for (int ksi = 0; ksi < KS; ksi++) s += g_p2p[ksi][p];
        p2s[p] = s;
    }
    __syncthreads();

    // phase 2: each thread sums bf16x2 xp partials for (row, p-pair) items
    const uint32_t* xpw = (const uint32_t*)g_xp;
    #pragma unroll
    for (int i = t; i < 448; i += 256) {            // 16 rows x 28 pairs
        const int row = i / 28;
        const int pp  = i % 28;
        const size_t base = ((size_t)mtb * 128 + rbase % 2048 - mtb * 128 + rbase) ;
        (void)base;
        float s0 = 0.f, s1 = 0.f;
        const size_t off0 = ((size_t)mtb * MT + (rg * 16 + row)) * (NP / 2) + pp;
        #pragma unroll
        for (int ksi = 0; ksi < KS; ksi++) {
            uint32_t v = xpw[(size_t)ksi * (MTILES * MT * (NP / 2)) + off0];
            __nv_bfloat162 h = *(__nv_bfloat162*)&v;
            s0 += __bfloat162float(h.x);
            s1 += __bfloat162float(h.y);
        }
        if (pp < 25) {                               // pairs 0..24 cover p 0..49
            const int b = rbase + row;
            const float x2v = x2s[row];
            float d0 = x2v + p2s[pp * 2]     - 2.f * s0;
            float d1 = x2v + p2s[pp * 2 + 1] - 2.f * s1;
            *(float2*)&out[(size_t)b * P_DIM + pp * 2] =
                make_float2(d0 > 0.f ? d0 : 0.f, d1 > 0.f ? d1 : 0.f);
        }
    }
}

// ---------------------------------------------------------------------------
extern "C" void kernel_launch(void* const* d_in, const int* in_sizes, int n_in,
                              void* d_out, int out_size) {
    const float* x     = (const float*)d_in[0];
    const float* proto = (const float*)d_in[1];
    if (in_sizes[0] == P_DIM * K_DIM) {  // defensive: swap if order differs
        x     = (const float*)d_in[1];
        proto = (const float*)d_in[0];
    }
    float* out = (float*)d_out;

    cudaFuncSetAttribute(gemm_kernel,
                         cudaFuncAttributeMaxDynamicSharedMemorySize, SMEM_BYTES);

    gemm_kernel<<<dim3(MTILES, KS), 256, SMEM_BYTES>>>(x, proto);
    epilogue_kernel<<<128, 256>>>(out);
}

// round 10
// speedup vs baseline: 1.3596x; 1.3596x over previous
#include <cuda_runtime.h>
#include <cuda_bf16.h>
#include <cstdint>

// Problem constants
#define B_DIM   2048
#define P_DIM   50
#define K_DIM   28672            // 512*7*8
#define NP      56               // P padded to 56 (7 n8-tiles)
#define KS      28               // K splits (uniform NITER=32, grid 448)
#define KCHUNK  (K_DIM / KS)     // 1024
#define KB      32               // K floats per pipeline stage
#define NITER   (KCHUNK / KB)    // 32
#define MT      128              // M tile
#define MTILES  (B_DIM / MT)     // 16
#define STAGES  3

// Swizzled tiles: exact 128B rows, XOR granule swizzle -> conflict-free
#define AS_BYTES (MT * KB * 4)               // 16384
#define BS_BYTES (NP * KB * 4)               // 7168
#define STAGE_BYTES (AS_BYTES + BS_BYTES)    // 23552
#define SMEM_BYTES (STAGES * STAGE_BYTES)    // 70656  (< 72KB -> 3 CTAs/SM)

// Static device scratch (allocation-free rule)
__device__ __nv_bfloat16 g_xp[(size_t)KS * MTILES * MT * NP];   // 6.4 MB (bf16)
__device__ float g_x2[(size_t)KS * B_DIM];                       // 229 KB
__device__ float g_p2p[KS][NP];                                  // p2 partials per ks

// ---------------------------------------------------------------------------
__device__ __forceinline__ void cpa16(uint32_t saddr, const void* gaddr) {
    asm volatile("cp.async.cg.shared.global [%0], [%1], 16;\n"
                 :: "r"(saddr), "l"(gaddr));
}
// zero-fill variant: src-size=0 reads nothing, fills 16B of zeros
__device__ __forceinline__ void cpa16z(uint32_t saddr, const void* gaddr, int srcsz) {
    asm volatile("cp.async.cg.shared.global [%0], [%1], 16, %2;\n"
                 :: "r"(saddr), "l"(gaddr), "r"(srcsz));
}
__device__ __forceinline__ void cpa_commit() {
    asm volatile("cp.async.commit_group;\n" ::: "memory");
}
__device__ __forceinline__ void cpa_wait2() {
    asm volatile("cp.async.wait_group 2;\n" ::: "memory");
}
__device__ __forceinline__ uint32_t pack_bf16x2(float2 v) {
    __nv_bfloat162 h = __floats2bfloat162_rn(v.x, v.y);
    return *(uint32_t*)&h;
}

// ---------------------------------------------------------------------------
// Fused GEMM (EXACT R8 code — measured 45us, do not touch):
// x fp32 + proto fp32 staged via cp.async (3 stages, XOR swizzle),
// in-register bf16 convert, x^2 (all blocks) and p^2 (mt==0 blocks) fused.
// grid (MTILES, KS) = 448 blocks, 256 threads = 8 warps.
// Skeleton: sync -> issue(it+2) -> wait2 -> sync -> compute (race-safe).
// ---------------------------------------------------------------------------
__global__ void __launch_bounds__(256, 3) gemm_kernel(
        const float* __restrict__ x, const float* __restrict__ proto) {
    extern __shared__ char smem[];

    const int mt   = blockIdx.x;
    const int ks   = blockIdx.y;
    const int t    = threadIdx.x;
    const int warp = t >> 5;
    const int lane = t & 31;
    const int q    = lane & 3;
    const int rr   = lane >> 2;       // 0..7
    const int b0   = mt * MT;
    const int k0   = ks * KCHUNK;

    // --- cp.async mappings ---
    const int xrr = t >> 3;           // 0..31
    const int xch = t & 7;            // granule 0..7 (row = 8 granules = 128B)
    const float* xg0 = x + (size_t)(b0 + xrr) * K_DIM + k0 + xch * 4;
    const uint32_t a_sw = (uint32_t)(xch ^ ((xrr & 3) << 1));

    const int prr = t >> 2;           // 0..63 (only < NP participate)
    const int pch = t & 3;
    const float* pg0 = proto + (size_t)prr * K_DIM + k0 + pch * 4;
    const uint32_t b_sw0 = (uint32_t)( pch      ^ ((prr & 3) << 1));
    const uint32_t b_sw1 = (uint32_t)((pch + 4) ^ ((prr & 3) << 1));
    const int psz = (prr < P_DIM) ? 16 : 0;

    const uint32_t smem_u = (uint32_t)__cvta_generic_to_shared(smem);

    auto issue = [&](int stage, int chunk) {
        const uint32_t sb = smem_u + (uint32_t)(stage * STAGE_BYTES);
        const float* xg = xg0 + chunk * KB;
        #pragma unroll
        for (int pass = 0; pass < 4; pass++) {
            cpa16(sb + (uint32_t)((xrr + pass * 32) * 128) + (a_sw << 4),
                  xg + (size_t)(pass * 32) * K_DIM);
        }
        if (prr < NP) {
            const float* pg = pg0 + chunk * KB;
            const uint32_t bb = sb + AS_BYTES + (uint32_t)(prr * 128);
            cpa16z(bb + (b_sw0 << 4), pg,      psz);
            cpa16z(bb + (b_sw1 << 4), pg + 16, psz);
        }
        cpa_commit();
    };

    // prologue
    issue(0, 0);
    issue(1, 1);

    // fragment rows
    const int r0 = warp * 16 + rr;
    const int r1 = r0 + 8;
    const uint32_t swf = (uint32_t)((rr & 3) << 1);
    const int qg = q >> 1;
    const int qp = (q & 1) << 3;

    float acc[7][4];
    #pragma unroll
    for (int j = 0; j < 7; j++)
        #pragma unroll
        for (int c = 0; c < 4; c++) acc[j][c] = 0.f;
    float x2a = 0.f, x2b = 0.f;
    float p2a[7];
    #pragma unroll
    for (int j = 0; j < 7; j++) p2a[j] = 0.f;

    int stage = 0;
    for (int it = 0; it < NITER; ++it) {
        __syncthreads();                 // stage (it+2)%3 free to overwrite
        const int nxt = it + 2;
        if (nxt < NITER) issue((stage + 2 >= STAGES) ? stage + 2 - STAGES : stage + 2, nxt);
        else             cpa_commit();   // keep group counting uniform
        cpa_wait2();                     // my copies for chunk `it` complete
        __syncthreads();                 // ALL threads' copies for chunk `it` visible

        const char* sb = smem + stage * STAGE_BYTES;
        const char* bbase = sb + AS_BYTES;
        if (++stage == STAGES) stage = 0;

        #pragma unroll
        for (int kk = 0; kk < 2; ++kk) {
            const uint32_t g0 = (uint32_t)(kk * 4 + qg);
            const uint32_t o_lo = ((g0 ^ swf) << 4) + qp;
            const uint32_t o_hi = (((g0 + 2) ^ swf) << 4) + qp;
            float2 a00 = *(const float2*)(sb + r0 * 128 + o_lo);
            float2 a01 = *(const float2*)(sb + r0 * 128 + o_hi);
            float2 a10 = *(const float2*)(sb + r1 * 128 + o_lo);
            float2 a11 = *(const float2*)(sb + r1 * 128 + o_hi);
            x2a += a00.x * a00.x + a00.y * a00.y + a01.x * a01.x + a01.y * a01.y;
            x2b += a10.x * a10.x + a10.y * a10.y + a11.x * a11.x + a11.y * a11.y;
            uint32_t A0 = pack_bf16x2(a00);
            uint32_t A1 = pack_bf16x2(a10);
            uint32_t A2 = pack_bf16x2(a01);
            uint32_t A3 = pack_bf16x2(a11);
            #pragma unroll
            for (int j = 0; j < 7; j++) {
                const int n = j * 8 + rr;
                const char* brow = bbase + n * 128;
                float2 b0 = *(const float2*)(brow + o_lo);
                float2 b1 = *(const float2*)(brow + o_hi);
                if (mt == 0)
                    p2a[j] += b0.x * b0.x + b0.y * b0.y + b1.x * b1.x + b1.y * b1.y;
                uint32_t B0 = pack_bf16x2(b0);
                uint32_t B1 = pack_bf16x2(b1);
                asm volatile(
                    "mma.sync.aligned.m16n8k16.row.col.f32.bf16.bf16.f32 "
                    "{%0,%1,%2,%3}, {%4,%5,%6,%7}, {%8,%9}, {%0,%1,%2,%3};\n"
                    : "+f"(acc[j][0]), "+f"(acc[j][1]), "+f"(acc[j][2]), "+f"(acc[j][3])
                    : "r"(A0), "r"(A1), "r"(A2), "r"(A3), "r"(B0), "r"(B1));
            }
        }
    }

    // xp partials in bf16 (private scratch slice per block — deterministic)
    __nv_bfloat16* outp = g_xp + ((size_t)ks * MTILES + mt) * (MT * NP);
    const int ccol = q * 2;
    #pragma unroll
    for (int j = 0; j < 7; j++) {
        const int n = j * 8 + ccol;
        *(uint32_t*)&outp[(size_t)r0 * NP + n] = pack_bf16x2(make_float2(acc[j][0], acc[j][1]));
        *(uint32_t*)&outp[(size_t)r1 * NP + n] = pack_bf16x2(make_float2(acc[j][2], acc[j][3]));
    }

    // x^2 partials: quad reduce (lanes differ only in k coverage)
    x2a += __shfl_xor_sync(0xffffffffu, x2a, 1);
    x2a += __shfl_xor_sync(0xffffffffu, x2a, 2);
    x2b += __shfl_xor_sync(0xffffffffu, x2b, 1);
    x2b += __shfl_xor_sync(0xffffffffu, x2b, 2);
    if (q == 0) {
        g_x2[(size_t)ks * B_DIM + b0 + r0] = x2a;
        g_x2[(size_t)ks * B_DIM + b0 + r1] = x2b;
    }

    // p^2 partials for this k-chunk (identical in every warp; warp 0 writes)
    if (mt == 0 && warp == 0) {
        #pragma unroll
        for (int j = 0; j < 7; j++) {
            float s = p2a[j];
            s += __shfl_xor_sync(0xffffffffu, s, 1);
            s += __shfl_xor_sync(0xffffffffu, s, 2);
            if (q == 0) g_p2p[ks][j * 8 + rr] = s;
        }
    }
}

// ---------------------------------------------------------------------------
// Epilogue v3: one output pair-item per thread, 448 blocks x 128 threads.
// Thread i maps DIRECTLY onto g_xp word layout (i = mt*3584 + r*28 + pp):
// the 28 per-ks xp loads are perfectly coalesced 128B lines, full MLP.
// x2/p2 sums are broadcast / L2-resident loads.
// ---------------------------------------------------------------------------
#define XP_SLICE_W (MTILES * MT * (NP / 2))   // 57344 words per ks slice

__global__ void __launch_bounds__(128) epilogue_kernel(float* __restrict__ out) {
    const int i  = blockIdx.x * 128 + threadIdx.x;   // 0..57343
    const int pp = i % 28;                           // bf16x2 pair index
    const int b  = i / 28;                           // output row 0..2047

    // xp: 28 coalesced, independent loads (stride = one slice = 229 KB)
    const uint32_t* xpw = (const uint32_t*)g_xp;
    float s0 = 0.f, s1 = 0.f;
    #pragma unroll
    for (int ks = 0; ks < KS; ks++) {
        uint32_t v = xpw[(size_t)ks * XP_SLICE_W + i];
        __nv_bfloat162 h = *(__nv_bfloat162*)&v;
        s0 += __bfloat162float(h.x);
        s1 += __bfloat162float(h.y);
    }

    // x2: 28 broadcast loads (same addr for the 28 threads sharing row b; L2-hot)
    float x2 = 0.f;
    #pragma unroll
    for (int ks = 0; ks < KS; ks++) x2 += g_x2[(size_t)ks * B_DIM + b];

    // p2: tiny table, L2/L1-hot
    float p20 = 0.f, p21 = 0.f;
    #pragma unroll
    for (int ks = 0; ks < KS; ks++) {
        p20 += g_p2p[ks][pp * 2];
        p21 += g_p2p[ks][pp * 2 + 1];
    }

    if (pp < 25) {   // pairs 0..24 cover p 0..49
        float d0 = x2 + p20 - 2.f * s0;
        float d1 = x2 + p21 - 2.f * s1;
        *(float2*)&out[(size_t)b * P_DIM + pp * 2] =
            make_float2(d0 > 0.f ? d0 : 0.f, d1 > 0.f ? d1 : 0.f);
    }
}

// ---------------------------------------------------------------------------
extern "C" void kernel_launch(void* const* d_in, const int* in_sizes, int n_in,
                              void* d_out, int out_size) {
    const float* x     = (const float*)d_in[0];
    const float* proto = (const float*)d_in[1];
    if (in_sizes[0] == P_DIM * K_DIM) {  // defensive: swap if order differs
        x     = (const float*)d_in[1];
        proto = (const float*)d_in[0];
    }
    float* out = (float*)d_out;

    cudaFuncSetAttribute(gemm_kernel,
                         cudaFuncAttributeMaxDynamicSharedMemorySize, SMEM_BYTES);

    gemm_kernel<<<dim3(MTILES, KS), 256, SMEM_BYTES>>>(x, proto);
    epilogue_kernel<<<448, 128>>>(out);
}

// round 11
// speedup vs baseline: 1.3745x; 1.0110x over previous
#include <cuda_runtime.h>
#include <cuda_bf16.h>
#include <cstdint>

// Problem constants
#define B_DIM   2048
#define P_DIM   50
#define K_DIM   28672            // 512*7*8
#define NP      56               // P padded to 56 (7 n8-tiles)
#define KS      28               // K splits (uniform NITER=32, grid 448)
#define KCHUNK  (K_DIM / KS)     // 1024
#define KB      32               // K floats per pipeline stage
#define NITER   (KCHUNK / KB)    // 32
#define MT      128              // M tile
#define MTILES  (B_DIM / MT)     // 16
#define STAGES  3

// Swizzled tiles: exact 128B rows, XOR granule swizzle -> conflict-free
#define AS_BYTES (MT * KB * 4)               // 16384
#define BS_BYTES (NP * KB * 4)               // 7168
#define STAGE_BYTES (AS_BYTES + BS_BYTES)    // 23552
#define SMEM_BYTES (STAGES * STAGE_BYTES)    // 70656  (< 72KB -> 3 CTAs/SM)

// ---------------------------------------------------------------------------
__device__ __forceinline__ void cpa16(uint32_t saddr, const void* gaddr) {
    asm volatile("cp.async.cg.shared.global [%0], [%1], 16;\n"
                 :: "r"(saddr), "l"(gaddr));
}
// zero-fill variant: src-size=0 reads nothing, fills 16B of zeros
__device__ __forceinline__ void cpa16z(uint32_t saddr, const void* gaddr, int srcsz) {
    asm volatile("cp.async.cg.shared.global [%0], [%1], 16, %2;\n"
                 :: "r"(saddr), "l"(gaddr), "r"(srcsz));
}
__device__ __forceinline__ void cpa_commit() {
    asm volatile("cp.async.commit_group;\n" ::: "memory");
}
__device__ __forceinline__ void cpa_wait2() {
    asm volatile("cp.async.wait_group 2;\n" ::: "memory");
}
__device__ __forceinline__ uint32_t pack_bf16x2(float2 v) {
    __nv_bfloat162 h = __floats2bfloat162_rn(v.x, v.y);
    return *(uint32_t*)&h;
}

// ---------------------------------------------------------------------------
// Fused GEMM + distance accumulation (single kernel):
// R8's proven pipeline/core loop; each (mt,ks) block RED-adds its complete
// per-chunk contribution  x2^ks_b + p2^ks_p - 2*xp^ks  into out[b,p].
// out must be zeroed beforehand (memset node in the graph).
// grid (MTILES, KS) = 448 blocks, 256 threads = 8 warps.
// ---------------------------------------------------------------------------
__global__ void __launch_bounds__(256, 3) gemm_kernel(
        const float* __restrict__ x, const float* __restrict__ proto,
        float* __restrict__ out) {
    extern __shared__ char smem[];

    const int mt   = blockIdx.x;
    const int ks   = blockIdx.y;
    const int t    = threadIdx.x;
    const int warp = t >> 5;
    const int lane = t & 31;
    const int q    = lane & 3;
    const int rr   = lane >> 2;       // 0..7
    const int b0   = mt * MT;
    const int k0   = ks * KCHUNK;

    // --- cp.async mappings (R8) ---
    const int xrr = t >> 3;           // 0..31
    const int xch = t & 7;            // granule 0..7 (row = 8 granules = 128B)
    const float* xg0 = x + (size_t)(b0 + xrr) * K_DIM + k0 + xch * 4;
    const uint32_t a_sw = (uint32_t)(xch ^ ((xrr & 3) << 1));

    const int prr = t >> 2;           // 0..63 (only < NP participate)
    const int pch = t & 3;
    const float* pg0 = proto + (size_t)prr * K_DIM + k0 + pch * 4;
    const uint32_t b_sw0 = (uint32_t)( pch      ^ ((prr & 3) << 1));
    const uint32_t b_sw1 = (uint32_t)((pch + 4) ^ ((prr & 3) << 1));
    const int psz = (prr < P_DIM) ? 16 : 0;

    const uint32_t smem_u = (uint32_t)__cvta_generic_to_shared(smem);

    auto issue = [&](int stage, int chunk) {
        const uint32_t sb = smem_u + (uint32_t)(stage * STAGE_BYTES);
        const float* xg = xg0 + chunk * KB;
        #pragma unroll
        for (int pass = 0; pass < 4; pass++) {
            cpa16(sb + (uint32_t)((xrr + pass * 32) * 128) + (a_sw << 4),
                  xg + (size_t)(pass * 32) * K_DIM);
        }
        if (prr < NP) {
            const float* pg = pg0 + chunk * KB;
            const uint32_t bb = sb + AS_BYTES + (uint32_t)(prr * 128);
            cpa16z(bb + (b_sw0 << 4), pg,      psz);
            cpa16z(bb + (b_sw1 << 4), pg + 16, psz);
        }
        cpa_commit();
    };

    // prologue
    issue(0, 0);
    issue(1, 1);

    // fragment rows
    const int r0 = warp * 16 + rr;
    const int r1 = r0 + 8;
    const uint32_t swf = (uint32_t)((rr & 3) << 1);
    const int qg = q >> 1;
    const int qp = (q & 1) << 3;

    float acc[7][4];
    #pragma unroll
    for (int j = 0; j < 7; j++)
        #pragma unroll
        for (int c = 0; c < 4; c++) acc[j][c] = 0.f;
    float x2a = 0.f, x2b = 0.f;
    float p2a[7];
    #pragma unroll
    for (int j = 0; j < 7; j++) p2a[j] = 0.f;

    int stage = 0;
    for (int it = 0; it < NITER; ++it) {
        __syncthreads();                 // stage (it+2)%3 free to overwrite
        const int nxt = it + 2;
        if (nxt < NITER) issue((stage + 2 >= STAGES) ? stage + 2 - STAGES : stage + 2, nxt);
        else             cpa_commit();   // keep group counting uniform
        cpa_wait2();                     // my copies for chunk `it` complete
        __syncthreads();                 // ALL threads' copies for chunk `it` visible

        const char* sb = smem + stage * STAGE_BYTES;
        const char* bbase = sb + AS_BYTES;
        if (++stage == STAGES) stage = 0;

        #pragma unroll
        for (int kk = 0; kk < 2; ++kk) {
            const uint32_t g0 = (uint32_t)(kk * 4 + qg);
            const uint32_t o_lo = ((g0 ^ swf) << 4) + qp;
            const uint32_t o_hi = (((g0 + 2) ^ swf) << 4) + qp;
            float2 a00 = *(const float2*)(sb + r0 * 128 + o_lo);
            float2 a01 = *(const float2*)(sb + r0 * 128 + o_hi);
            float2 a10 = *(const float2*)(sb + r1 * 128 + o_lo);
            float2 a11 = *(const float2*)(sb + r1 * 128 + o_hi);
            x2a += a00.x * a00.x + a00.y * a00.y + a01.x * a01.x + a01.y * a01.y;
            x2b += a10.x * a10.x + a10.y * a10.y + a11.x * a11.x + a11.y * a11.y;
            uint32_t A0 = pack_bf16x2(a00);
            uint32_t A1 = pack_bf16x2(a10);
            uint32_t A2 = pack_bf16x2(a01);
            uint32_t A3 = pack_bf16x2(a11);
            #pragma unroll
            for (int j = 0; j < 7; j++) {
                const int n = j * 8 + rr;
                const char* brow = bbase + n * 128;
                float2 b0 = *(const float2*)(brow + o_lo);
                float2 b1 = *(const float2*)(brow + o_hi);
                p2a[j] += b0.x * b0.x + b0.y * b0.y + b1.x * b1.x + b1.y * b1.y;
                uint32_t B0 = pack_bf16x2(b0);
                uint32_t B1 = pack_bf16x2(b1);
                asm volatile(
                    "mma.sync.aligned.m16n8k16.row.col.f32.bf16.bf16.f32 "
                    "{%0,%1,%2,%3}, {%4,%5,%6,%7}, {%8,%9}, {%0,%1,%2,%3};\n"
                    : "+f"(acc[j][0]), "+f"(acc[j][1]), "+f"(acc[j][2]), "+f"(acc[j][3])
                    : "r"(A0), "r"(A1), "r"(A2), "r"(A3), "r"(B0), "r"(B1));
            }
        }
    }

    // --- block epilogue: RED-add full per-chunk contribution into out ---

    // x^2 per row (quad reduce; all 4 lanes end with the row sum)
    x2a += __shfl_xor_sync(0xffffffffu, x2a, 1);
    x2a += __shfl_xor_sync(0xffffffffu, x2a, 2);
    x2b += __shfl_xor_sync(0xffffffffu, x2b, 1);
    x2b += __shfl_xor_sync(0xffffffffu, x2b, 2);

    // p^2 per column via smem table (identical in every warp; warp 0 writes)
    __syncthreads();                      // done with pipeline smem
    float* p2s = (float*)smem;            // 56 floats
    if (warp == 0) {
        #pragma unroll
        for (int j = 0; j < 7; j++) {
            float s = p2a[j];
            s += __shfl_xor_sync(0xffffffffu, s, 1);
            s += __shfl_xor_sync(0xffffffffu, s, 2);
            if (q == 0) p2s[j * 8 + rr] = s;
        }
    }
    __syncthreads();

    // RED: out[b, n] += x2_row + p2_col - 2*xp   (relu deferred; dist >= 0)
    float* out0 = out + (size_t)(b0 + r0) * P_DIM;
    float* out1 = out + (size_t)(b0 + r1) * P_DIM;
    const int ccol = q * 2;
    #pragma unroll
    for (int j = 0; j < 7; j++) {
        const int n0 = j * 8 + ccol;
        const int n1 = n0 + 1;
        if (n0 < P_DIM) {
            const float pv0 = p2s[n0];
            atomicAdd(out0 + n0, x2a + pv0 - 2.f * acc[j][0]);
            atomicAdd(out1 + n0, x2b + pv0 - 2.f * acc[j][2]);
        }
        if (n1 < P_DIM) {
            const float pv1 = p2s[n1];
            atomicAdd(out0 + n1, x2a + pv1 - 2.f * acc[j][1]);
            atomicAdd(out1 + n1, x2b + pv1 - 2.f * acc[j][3]);
        }
    }
}

// ---------------------------------------------------------------------------
extern "C" void kernel_launch(void* const* d_in, const int* in_sizes, int n_in,
                              void* d_out, int out_size) {
    const float* x     = (const float*)d_in[0];
    const float* proto = (const float*)d_in[1];
    if (in_sizes[0] == P_DIM * K_DIM) {  // defensive: swap if order differs
        x     = (const float*)d_in[1];
        proto = (const float*)d_in[0];
    }
    float* out = (float*)d_out;

    cudaFuncSetAttribute(gemm_kernel,
                         cudaFuncAttributeMaxDynamicSharedMemorySize, SMEM_BYTES);

    cudaMemsetAsync(out, 0, (size_t)B_DIM * P_DIM * sizeof(float));
    gemm_kernel<<<dim3(MTILES, KS), 256, SMEM_BYTES>>>(x, proto, out);
}